// round 17
// baseline (speedup 1.0000x reference)
#include <cuda_runtime.h>
#include <cuda_bf16.h>
#include <math.h>
#include <stdint.h>

// ---------------------------------------------------------------------------
// RSSM scan: T=50, B=2048. GEMMs via mma.sync.m16n8k16 bf16 (base sm_103).
// Split-bf16 planes (hi=rn(v), lo=rn(v-hi)); GEMM = hi*hi + lo*hi + hi*lo.
// R15: BK=32 with combined [hi|lo] 128B SMEM rows -> 96.5KB smem, 2 CTAs/SM
// (__launch_bounds__(256,2)); per-i A fragments to fit 128 regs; BM=64
// variant for the N=512 GEMMs (128 CTAs instead of 64).
// ---------------------------------------------------------------------------

#define T_STEPS 50
#define BATCH   2048
#define BK      32
#define STAGES  3

typedef __nv_bfloat16 bf16;

// ---------------- scratch (no cudaMalloc allowed) ----------------
__device__ bf16 WsaH[1024 * 320],  WsaL[1024 * 320];
__device__ bf16 WihH[3072 * 1024], WihL[3072 * 1024];
__device__ bf16 WhhH[3072 * 1024], WhhL[3072 * 1024];
__device__ bf16 WpbH[1024 * 1024], WpbL[1024 * 1024];
__device__ bf16 WpsH[512 * 1024],  WpsL[512 * 1024];
__device__ bf16 WqbH[(size_t)1024 * 2048], WqbL[(size_t)1024 * 2048];
__device__ bf16 WqsH[512 * 1024],  WqsL[512 * 1024];
__device__ bf16 actPH[(size_t)T_STEPS * BATCH * 64], actPL[(size_t)T_STEPS * BATCH * 64];
__device__ bf16 statePH[BATCH * 256],  statePL[BATCH * 256];
__device__ bf16 belPH[BATCH * 1024],   belPL[BATCH * 1024];
__device__ bf16 rnnPH[BATCH * 1024],   rnnPL[BATCH * 1024];
__device__ bf16 hidPH[BATCH * 1024],   hidPL[BATCH * 1024];
__device__ bf16 obsPH[BATCH * 1024],   obsPL[BATCH * 1024];
__device__ float g_gates[(size_t)BATCH * 6144];
__device__ float g_head[BATCH * 512];

// ---------------- helpers ----------------
__device__ __forceinline__ uint32_t smem_u32(const void* p) {
    uint32_t a;
    asm("{ .reg .u64 t; cvta.to.shared.u64 t, %1; cvt.u32.u64 %0, t; }" : "=r"(a) : "l"(p));
    return a;
}
__device__ __forceinline__ void cp_async16(uint32_t dst, const void* src) {
    asm volatile("cp.async.cg.shared.global [%0], [%1], 16;" :: "r"(dst), "l"(src));
}
#define CP_COMMIT() asm volatile("cp.async.commit_group;" ::: "memory")

__device__ __forceinline__ void ldsm4(uint32_t& r0, uint32_t& r1, uint32_t& r2, uint32_t& r3,
                                      uint32_t addr) {
    asm volatile("ldmatrix.sync.aligned.m8n8.x4.shared.b16 {%0,%1,%2,%3}, [%4];"
                 : "=r"(r0), "=r"(r1), "=r"(r2), "=r"(r3) : "r"(addr));
}
__device__ __forceinline__ void mma_bf16(float* d,
                                         uint32_t a0, uint32_t a1, uint32_t a2, uint32_t a3,
                                         uint32_t b0, uint32_t b1) {
    asm volatile("mma.sync.aligned.m16n8k16.row.col.f32.bf16.bf16.f32 "
                 "{%0,%1,%2,%3}, {%4,%5,%6,%7}, {%8,%9}, {%0,%1,%2,%3};"
                 : "+f"(d[0]), "+f"(d[1]), "+f"(d[2]), "+f"(d[3])
                 : "r"(a0), "r"(a1), "r"(a2), "r"(a3), "r"(b0), "r"(b1));
}
__device__ __forceinline__ void split_bf(float v, bf16& h, bf16& l) {
    h = __float2bfloat16_rn(v);
    l = __float2bfloat16_rn(v - __bfloat162float(h));
}
__device__ __forceinline__ uint32_t pack2(bf16 x, bf16 y) {
    return ((uint32_t)__bfloat16_as_ushort(y) << 16) | __bfloat16_as_ushort(x);
}

// SMEM: [bias 512B | STAGES x (A-combined | B-combined)]
// combined row = 128B: chunks 0-3 = hi (k0..31), 4-7 = lo; phys chunk = c ^ (row&7)
#define SM_BIAS 0
#define SM_TILE 512
#define SMSZ(MI) (512 + STAGES * ((MI) * 32 * 128 + 128 * 128))

// ---------------------------------------------------------------------------
// MI=4: BM=128 (warp tile 64x32); MI=2: BM=64 (warp tile 32x32). BN=128.
template<int ACT, int OUTP, int MI>
__global__ __launch_bounds__(256, 2)
void gemm_bf(const bf16* __restrict__ A1h, const bf16* __restrict__ A1l, int lda1, int K1,
             const bf16* __restrict__ A2h, const bf16* __restrict__ A2l, int lda2,
             const bf16* __restrict__ Wh,  const bf16* __restrict__ Wl,  int ldw,
             const float* __restrict__ bias,
             float* __restrict__ C, bf16* __restrict__ Ch, bf16* __restrict__ Cl,
             int ldc, int coloff, int K)
{
    constexpr int ST_A = MI * 32 * 128;          // A tile bytes
    constexpr int STG  = ST_A + 128 * 128;       // stage bytes
    extern __shared__ char smem[];
    const uint32_t sb = smem_u32(smem);
    const int tid = threadIdx.x, lane = tid & 31, warp = tid >> 5;
    const int wm = warp & 1, wn = warp >> 1;     // 2 x 4 warp grid
    const int bm = blockIdx.y * (MI * 32), bn = blockIdx.x * 128;

    if (tid < 128) reinterpret_cast<float*>(smem + SM_BIAS)[tid] = bias[bn + tid];

    float acc[MI][4][4];
    #pragma unroll
    for (int i = 0; i < MI; i++)
        #pragma unroll
        for (int j = 0; j < 4; j++)
            #pragma unroll
            for (int e = 0; e < 4; e++) acc[i][j][e] = 0.0f;

    const int nkt = K / BK;

    // loader: one 128B combined row per thread (A rows first, then B rows)
    const int nAr = MI * 32;
    const bool ldact = tid < nAr + 128;
    const bool isA   = tid < nAr;
    const int  lr    = isA ? tid : tid - nAr;

    auto load_tile = [&](int kt, int buf) {
        if (!ldact) return;
        const int k0 = kt * BK;
        const uint32_t st = sb + SM_TILE + buf * STG;
        const bf16 *ph, *pl;
        uint32_t dst;
        if (isA) {
            if (k0 < K1) {
                ph = A1h + (size_t)(bm + lr) * lda1 + k0;
                pl = A1l + (size_t)(bm + lr) * lda1 + k0;
            } else {
                ph = A2h + (size_t)(bm + lr) * lda2 + (k0 - K1);
                pl = A2l + (size_t)(bm + lr) * lda2 + (k0 - K1);
            }
            dst = st + lr * 128;
        } else {
            ph = Wh + (size_t)(bn + lr) * ldw + k0;
            pl = Wl + (size_t)(bn + lr) * ldw + k0;
            dst = st + ST_A + lr * 128;
        }
        const int sw = lr & 7;
        #pragma unroll
        for (int c = 0; c < 4; c++) {
            cp_async16(dst + (((c)     ^ sw) << 4), ph + c * 8);
            cp_async16(dst + (((4 + c) ^ sw) << 4), pl + c * 8);
        }
    };

    #pragma unroll
    for (int s = 0; s < STAGES - 1; s++) {
        if (s < nkt) load_tile(s, s);
        CP_COMMIT();
    }

    // ldmatrix lane addressing
    const int arow_l = lane & 15;
    const int achk_l = lane >> 4;
    const int brow_l = (lane & 7) + ((lane & 16) ? 8 : 0);
    const int bchk_l = (lane >> 3) & 1;

    for (int kt = 0; kt < nkt; kt++) {
        const int buf = kt % STAGES;
        asm volatile("cp.async.wait_group %0;" :: "n"(STAGES - 2) : "memory");
        __syncthreads();

        const int nt = kt + STAGES - 1;
        if (nt < nkt) load_tile(nt, nt % STAGES);
        CP_COMMIT();

        const uint32_t st = sb + SM_TILE + buf * STG;

        #pragma unroll
        for (int s = 0; s < 2; s++) {            // 2 K16 steps per BK=32 tile
            uint32_t bh[2][4], bl[2][4];
            #pragma unroll
            for (int j2 = 0; j2 < 2; j2++) {
                const int row = wn * 32 + j2 * 16 + brow_l;
                const int sw = row & 7;
                const uint32_t ra = st + ST_A + row * 128;
                ldsm4(bh[j2][0], bh[j2][1], bh[j2][2], bh[j2][3],
                      ra + (((2 * s + bchk_l) ^ sw) << 4));
                ldsm4(bl[j2][0], bl[j2][1], bl[j2][2], bl[j2][3],
                      ra + (((4 + 2 * s + bchk_l) ^ sw) << 4));
            }
            #pragma unroll
            for (int i = 0; i < MI; i++) {
                const int row = wm * (MI * 16) + i * 16 + arow_l;
                const int sw = row & 7;
                const uint32_t ra = st + row * 128;
                uint32_t ah0, ah1, ah2, ah3, al0, al1, al2, al3;
                ldsm4(ah0, ah1, ah2, ah3, ra + (((2 * s + achk_l) ^ sw) << 4));
                ldsm4(al0, al1, al2, al3, ra + (((4 + 2 * s + achk_l) ^ sw) << 4));
                #pragma unroll
                for (int j2 = 0; j2 < 2; j2++)
                    #pragma unroll
                    for (int jo = 0; jo < 2; jo++) {
                        const int j = 2 * j2 + jo;
                        mma_bf16(acc[i][j], al0, al1, al2, al3,
                                 bh[j2][2 * jo], bh[j2][2 * jo + 1]);
                        mma_bf16(acc[i][j], ah0, ah1, ah2, ah3,
                                 bl[j2][2 * jo], bl[j2][2 * jo + 1]);
                        mma_bf16(acc[i][j], ah0, ah1, ah2, ah3,
                                 bh[j2][2 * jo], bh[j2][2 * jo + 1]);
                    }
            }
        }
        __syncthreads();
    }

    // epilogue
    const float* biasS = reinterpret_cast<const float*>(smem + SM_BIAS);
    const int er = lane >> 2, ec = (lane & 3) * 2;
    #pragma unroll
    for (int i = 0; i < MI; i++) {
        const int row0 = bm + wm * (MI * 16) + i * 16 + er;
        #pragma unroll
        for (int j = 0; j < 4; j++) {
            const int col = wn * 32 + j * 8 + ec;
            float b0 = biasS[col], b1 = biasS[col + 1];
            float v0x = acc[i][j][0] + b0, v0y = acc[i][j][1] + b1;
            float v1x = acc[i][j][2] + b0, v1y = acc[i][j][3] + b1;
            if (ACT == 1) {
                v0x = fmaxf(v0x, 0.0f); v0y = fmaxf(v0y, 0.0f);
                v1x = fmaxf(v1x, 0.0f); v1y = fmaxf(v1y, 0.0f);
            }
            if (OUTP == 0) {
                *reinterpret_cast<float2*>(C + (size_t)row0 * ldc + coloff + bn + col) =
                    make_float2(v0x, v0y);
                *reinterpret_cast<float2*>(C + (size_t)(row0 + 8) * ldc + coloff + bn + col) =
                    make_float2(v1x, v1y);
            } else {
                bf16 hx, lx, hy, ly;
                split_bf(v0x, hx, lx); split_bf(v0y, hy, ly);
                *reinterpret_cast<uint32_t*>(Ch + (size_t)row0 * ldc + bn + col) = pack2(hx, hy);
                *reinterpret_cast<uint32_t*>(Cl + (size_t)row0 * ldc + bn + col) = pack2(lx, ly);
                split_bf(v1x, hx, lx); split_bf(v1y, hy, ly);
                *reinterpret_cast<uint32_t*>(Ch + (size_t)(row0 + 8) * ldc + bn + col) = pack2(hx, hy);
                *reinterpret_cast<uint32_t*>(Cl + (size_t)(row0 + 8) * ldc + bn + col) = pack2(lx, ly);
            }
        }
    }
}

// ---------------- conversion: fp32 [R x Ks] -> bf16 planes [R x Kd], zero-pad
__global__ void split_pad(const float* __restrict__ src,
                          bf16* __restrict__ hi, bf16* __restrict__ lo,
                          int Ks, int Kd, int total)
{
    int idx = blockIdx.x * blockDim.x + threadIdx.x;
    if (idx >= total) return;
    int r = idx / Kd, k = idx - r * Kd;
    float v = (k < Ks) ? src[(size_t)r * Ks + k] : 0.0f;
    bf16 h, l;
    split_bf(v, h, l);
    hi[idx] = h; lo[idx] = l;
}

// ---------------- elementwise kernels ----------------
__device__ __forceinline__ float sigmoidf_(float x) { return 1.0f / (1.0f + expf(-x)); }

__global__ void gru_kernel(const float* __restrict__ gates,
                           const float* __restrict__ h,
                           float* __restrict__ b1,
                           bf16* __restrict__ pH, bf16* __restrict__ pL)
{
    int i = blockIdx.x * blockDim.x + threadIdx.x;
    int b = i >> 10, j = i & 1023;
    const float* g = gates + (size_t)b * 6144;
    float ir = g[j],        iz = g[j + 1024], in = g[j + 2048];
    float hr = g[j + 3072], hz = g[j + 4096], hn = g[j + 5120];
    float rr = sigmoidf_(ir + hr);
    float z  = sigmoidf_(iz + hz);
    float n  = tanhf(in + rr * hn);
    float v  = (1.0f - z) * n + z * h[i];
    b1[i] = v;
    bf16 hh, ll; split_bf(v, hh, ll);
    pH[i] = hh; pL[i] = ll;
}

template<int PLANES>
__global__ void sample_kernel(const float* __restrict__ raw,
                              const float* __restrict__ noise,
                              float* __restrict__ states,
                              float* __restrict__ means,
                              float* __restrict__ stds,
                              bf16* __restrict__ pH, bf16* __restrict__ pL)
{
    int i = blockIdx.x * blockDim.x + threadIdx.x;
    int b = i >> 8, n = i & 255;
    const float* rp = raw + (size_t)b * 512;
    float m  = rp[n];
    float x  = expf(rp[n + 256]);
    float sp = (x > 20.0f) ? x : log1pf(expf(x));
    float sd = sp + 0.1f;
    float s  = m + sd * noise[i];
    states[i] = s;
    means[i]  = m;
    stds[i]   = sd;
    if (PLANES) {
        bf16 hh, ll; split_bf(s, hh, ll);
        pH[i] = hh; pL[i] = ll;
    }
}

// ---------------------------------------------------------------------------
extern "C" void kernel_launch(void* const* d_in, const int* in_sizes, int n_in,
                              void* d_out, int out_size)
{
    (void)in_sizes; (void)n_in; (void)out_size;
    const float* prev_state  = (const float*)d_in[0];
    const float* actions     = (const float*)d_in[1];
    const float* prev_belief = (const float*)d_in[2];
    const float* obs         = (const float*)d_in[3];
    const float* prior_noise = (const float*)d_in[4];
    const float* post_noise  = (const float*)d_in[5];
    const float* W_sa = (const float*)d_in[6];   const float* b_sa = (const float*)d_in[7];
    const float* W_ih = (const float*)d_in[8];   const float* W_hh = (const float*)d_in[9];
    const float* b_ih = (const float*)d_in[10];  const float* b_hh = (const float*)d_in[11];
    const float* W_pb = (const float*)d_in[12];  const float* b_pb = (const float*)d_in[13];
    const float* W_ps = (const float*)d_in[14];  const float* b_ps = (const float*)d_in[15];
    const float* W_qb = (const float*)d_in[16];  const float* b_qb = (const float*)d_in[17];
    const float* W_qs = (const float*)d_in[18];  const float* b_qs = (const float*)d_in[19];

    float* out = (float*)d_out;
    const size_t TB = (size_t)T_STEPS * BATCH;
    float* beliefs      = out;
    float* prior_states = beliefs      + TB * 1024;
    float* prior_means  = prior_states + TB * 256;
    float* prior_stds   = prior_means  + TB * 256;
    float* post_states  = prior_stds   + TB * 256;
    float* post_means   = post_states  + TB * 256;
    float* post_stds    = post_means   + TB * 256;

    bf16 *wsaH, *wsaL, *wihH, *wihL, *whhH, *whhL, *wpbH, *wpbL,
         *wpsH, *wpsL, *wqbH, *wqbL, *wqsH, *wqsL,
         *actH, *actL, *stH, *stL, *beH, *beL, *rnH, *rnL, *hiH, *hiL, *obH, *obL;
    float *gates, *head;
    cudaGetSymbolAddress((void**)&wsaH, WsaH); cudaGetSymbolAddress((void**)&wsaL, WsaL);
    cudaGetSymbolAddress((void**)&wihH, WihH); cudaGetSymbolAddress((void**)&wihL, WihL);
    cudaGetSymbolAddress((void**)&whhH, WhhH); cudaGetSymbolAddress((void**)&whhL, WhhL);
    cudaGetSymbolAddress((void**)&wpbH, WpbH); cudaGetSymbolAddress((void**)&wpbL, WpbL);
    cudaGetSymbolAddress((void**)&wpsH, WpsH); cudaGetSymbolAddress((void**)&wpsL, WpsL);
    cudaGetSymbolAddress((void**)&wqbH, WqbH); cudaGetSymbolAddress((void**)&wqbL, WqbL);
    cudaGetSymbolAddress((void**)&wqsH, WqsH); cudaGetSymbolAddress((void**)&wqsL, WqsL);
    cudaGetSymbolAddress((void**)&actH, actPH); cudaGetSymbolAddress((void**)&actL, actPL);
    cudaGetSymbolAddress((void**)&stH, statePH); cudaGetSymbolAddress((void**)&stL, statePL);
    cudaGetSymbolAddress((void**)&beH, belPH);   cudaGetSymbolAddress((void**)&beL, belPL);
    cudaGetSymbolAddress((void**)&rnH, rnnPH);   cudaGetSymbolAddress((void**)&rnL, rnnPL);
    cudaGetSymbolAddress((void**)&hiH, hidPH);   cudaGetSymbolAddress((void**)&hiL, hidPL);
    cudaGetSymbolAddress((void**)&obH, obsPH);   cudaGetSymbolAddress((void**)&obL, obsPL);
    cudaGetSymbolAddress((void**)&gates, g_gates);
    cudaGetSymbolAddress((void**)&head,  g_head);

    const int SZ4 = SMSZ(4), SZ2 = SMSZ(2);
    cudaFuncSetAttribute(gemm_bf<0, 0, 4>, cudaFuncAttributeMaxDynamicSharedMemorySize, SZ4);
    cudaFuncSetAttribute(gemm_bf<1, 1, 4>, cudaFuncAttributeMaxDynamicSharedMemorySize, SZ4);
    cudaFuncSetAttribute(gemm_bf<0, 0, 2>, cudaFuncAttributeMaxDynamicSharedMemorySize, SZ2);

    auto conv = [&](const float* s, bf16* h, bf16* l, int R, int Ks, int Kd) {
        int tot = R * Kd;
        split_pad<<<(tot + 255) / 256, 256>>>(s, h, l, Ks, Kd, tot);
    };

    conv(W_sa, wsaH, wsaL, 1024, 288, 320);
    conv(W_ih, wihH, wihL, 3072, 1024, 1024);
    conv(W_hh, whhH, whhL, 3072, 1024, 1024);
    conv(W_pb, wpbH, wpbL, 1024, 1024, 1024);
    conv(W_ps, wpsH, wpsL, 512, 1024, 1024);
    conv(W_qb, wqbH, wqbL, 1024, 2048, 2048);
    conv(W_qs, wqsH, wqsL, 512, 1024, 1024);
    conv(actions, actH, actL, T_STEPS * BATCH, 32, 64);
    conv(prev_state, stH, stL, BATCH, 256, 256);
    conv(prev_belief, beH, beL, BATCH, 1024, 1024);

    const int NOCAT = 1 << 30;
    const dim3 blk(256);
    const dim3 g1024(8, 16), g3072(24, 16), g512(4, 32);

    for (int t = 0; t < T_STEPS; t++) {
        const float* h_prev = (t == 0) ? prev_belief : beliefs + (size_t)(t - 1) * BATCH * 1024;
        float* bel_t = beliefs + (size_t)t * BATCH * 1024;

        // rnn = relu([state|a_t] @ W_sa^T + b_sa)  K=320 (padded), K1=256 -> planes
        gemm_bf<1, 1, 4><<<g1024, blk, SZ4>>>(
            stH, stL, 256, 256,
            actH + (size_t)t * BATCH * 64, actL + (size_t)t * BATCH * 64, 64,
            wsaH, wsaL, 320, b_sa, nullptr, rnH, rnL, 1024, 0, 320);
        // gi / gh -> fp32 gates
        gemm_bf<0, 0, 4><<<g3072, blk, SZ4>>>(
            rnH, rnL, 1024, NOCAT, nullptr, nullptr, 0,
            wihH, wihL, 1024, b_ih, gates, nullptr, nullptr, 6144, 0, 1024);
        gemm_bf<0, 0, 4><<<g3072, blk, SZ4>>>(
            beH, beL, 1024, NOCAT, nullptr, nullptr, 0,
            whhH, whhL, 1024, b_hh, gates, nullptr, nullptr, 6144, 3072, 1024);
        gru_kernel<<<(BATCH * 1024) / 256, 256>>>(gates, h_prev, bel_t, beH, beL);

        // prior head
        gemm_bf<1, 1, 4><<<g1024, blk, SZ4>>>(
            beH, beL, 1024, NOCAT, nullptr, nullptr, 0,
            wpbH, wpbL, 1024, b_pb, nullptr, hiH, hiL, 1024, 0, 1024);
        gemm_bf<0, 0, 2><<<g512, blk, SZ2>>>(
            hiH, hiL, 1024, NOCAT, nullptr, nullptr, 0,
            wpsH, wpsL, 1024, b_ps, head, nullptr, nullptr, 512, 0, 1024);
        sample_kernel<0><<<(BATCH * 256) / 256, 256>>>(head,
            prior_noise + (size_t)t * BATCH * 256,
            prior_states + (size_t)t * BATCH * 256,
            prior_means  + (size_t)t * BATCH * 256,
            prior_stds   + (size_t)t * BATCH * 256, nullptr, nullptr);

        // posterior head: convert obs_t, then [bel|obs] K=2048, K1=1024
        conv(obs + (size_t)t * BATCH * 1024, obH, obL, BATCH, 1024, 1024);
        gemm_bf<1, 1, 4><<<g1024, blk, SZ4>>>(
            beH, beL, 1024, 1024, obH, obL, 1024,
            wqbH, wqbL, 2048, b_qb, nullptr, hiH, hiL, 1024, 0, 2048);
        gemm_bf<0, 0, 2><<<g512, blk, SZ2>>>(
            hiH, hiL, 1024, NOCAT, nullptr, nullptr, 0,
            wqsH, wqsL, 1024, b_qs, head, nullptr, nullptr, 512, 0, 1024);
        sample_kernel<1><<<(BATCH * 256) / 256, 256>>>(head,
            post_noise + (size_t)t * BATCH * 256,
            post_states + (size_t)t * BATCH * 256,
            post_means  + (size_t)t * BATCH * 256,
            post_stds   + (size_t)t * BATCH * 256, stH, stL);
    }
}